// round 10
// baseline (speedup 1.0000x reference)
#include <cuda_runtime.h>

// out[b, q] = cos(x[b, q] + w[q]),  x: [4194304, 24] f32, w: [24] f32.
// Persistent grid-stride version of the R8 config (best measured: 84.1%
// DRAM, 48 regs natural). v8 (256-bit) accesses; v8 index i uses weight
// octet (i % 3). THREADS=192 divisible by 3 and both the block offset
// (768*bid) and loop stride (grid*768) divisible by 3 => octet index is
// the loop-invariant (tid % 3), loaded once per CTA lifetime.

#define THREADS 192
#define U 4
#define BLOCKS_PER_SM 6
#define NUM_SMS 148

__device__ __forceinline__ void ld_v8_cs(const float* p, float* v) {
    asm volatile("ld.global.cs.v8.f32 {%0,%1,%2,%3,%4,%5,%6,%7}, [%8];"
                 : "=f"(v[0]), "=f"(v[1]), "=f"(v[2]), "=f"(v[3]),
                   "=f"(v[4]), "=f"(v[5]), "=f"(v[6]), "=f"(v[7])
                 : "l"(p));
}

__device__ __forceinline__ void st_v8_cs(float* p, const float* v) {
    asm volatile("st.global.cs.v8.f32 [%0], {%1,%2,%3,%4,%5,%6,%7,%8};"
                 :: "l"(p),
                    "f"(v[0]), "f"(v[1]), "f"(v[2]), "f"(v[3]),
                    "f"(v[4]), "f"(v[5]), "f"(v[6]), "f"(v[7])
                 : "memory");
}

__global__ __launch_bounds__(THREADS, BLOCKS_PER_SM)
void qfl_cos_kernel(const float* __restrict__ x,
                    const float* __restrict__ w,
                    float* __restrict__ out,
                    int n8) {
    int tid    = threadIdx.x;
    int stride = gridDim.x * (THREADS * U);          // divisible by 3

    // Loop-invariant weight octet: w[(tid%3)*8 .. +8), loaded once.
    const float* wp = w + (tid % 3) * 8;
    float W[8];
#pragma unroll
    for (int j = 0; j < 8; j++) W[j] = __ldg(wp + j);

    for (int base8 = blockIdx.x * (THREADS * U) + tid;
         base8 < n8; base8 += stride) {

        if (base8 + (U - 1) * THREADS < n8) {
            float v[U][8];
#pragma unroll
            for (int k = 0; k < U; k++)
                ld_v8_cs(x + (size_t)(base8 + k * THREADS) * 8, v[k]);

#pragma unroll
            for (int k = 0; k < U; k++) {
                float r[8];
#pragma unroll
                for (int j = 0; j < 8; j++)
                    r[j] = __cosf(v[k][j] + W[j]);
                st_v8_cs(out + (size_t)(base8 + k * THREADS) * 8, r);
            }
        } else {
            // Partial chunk at the very end of the range.
#pragma unroll
            for (int k = 0; k < U; k++) {
                int i = base8 + k * THREADS;
                if (i < n8) {
                    float v[8], r[8];
                    ld_v8_cs(x + (size_t)i * 8, v);
#pragma unroll
                    for (int j = 0; j < 8; j++)
                        r[j] = __cosf(v[j] + W[j]);
                    st_v8_cs(out + (size_t)i * 8, r);
                }
            }
        }
    }
}

extern "C" void kernel_launch(void* const* d_in, const int* in_sizes, int n_in,
                              void* d_out, int out_size) {
    const float* x = (const float*)d_in[0];
    const float* w = (const float*)d_in[1];
    float* out = (float*)d_out;

    int n  = in_sizes[0];   // 100663296
    int n8 = n >> 3;        // 12582912 v8s

    int blocks = NUM_SMS * BLOCKS_PER_SM;   // 888 persistent CTAs
    qfl_cos_kernel<<<blocks, THREADS>>>(x, w, out, n8);
}

// round 11
// speedup vs baseline: 1.1186x; 1.1186x over previous
#include <cuda_runtime.h>

// out[b, q] = cos(x[b, q] + w[q]),  x: [4194304, 24] f32, w: [24] f32.
// Flat-grid (R8 shape — best measured DRAM 84.1%), depth pushed to U=6:
// six front-batched LDG.256 per thread = 192B in flight/thread. v8 index
// i uses weight octet (i % 3); THREADS=192 divisible by 3 and per-block
// offset (1152*bid) divisible by 3 => octet index is loop-invariant
// (tid % 3). launch_bounds(192,5) = 68-reg cap: generous, so ptxas keeps
// its natural batched schedule (tight caps broke it in R9/R10).

#define THREADS 192
#define U 6

__device__ __forceinline__ void ld_v8_cs(const float* p, float* v) {
    asm volatile("ld.global.cs.v8.f32 {%0,%1,%2,%3,%4,%5,%6,%7}, [%8];"
                 : "=f"(v[0]), "=f"(v[1]), "=f"(v[2]), "=f"(v[3]),
                   "=f"(v[4]), "=f"(v[5]), "=f"(v[6]), "=f"(v[7])
                 : "l"(p));
}

__device__ __forceinline__ void st_v8_cs(float* p, const float* v) {
    asm volatile("st.global.cs.v8.f32 [%0], {%1,%2,%3,%4,%5,%6,%7,%8};"
                 :: "l"(p),
                    "f"(v[0]), "f"(v[1]), "f"(v[2]), "f"(v[3]),
                    "f"(v[4]), "f"(v[5]), "f"(v[6]), "f"(v[7])
                 : "memory");
}

__global__ __launch_bounds__(THREADS, 5)
void qfl_cos_kernel(const float* __restrict__ x,
                    const float* __restrict__ w,
                    float* __restrict__ out,
                    int n8) {
    int tid   = threadIdx.x;
    int base8 = blockIdx.x * (THREADS * U) + tid;

    // Loop-invariant weight octet: w[(tid%3)*8 .. +8)
    const float* wp = w + (tid % 3) * 8;
    float W[8];
#pragma unroll
    for (int j = 0; j < 8; j++) W[j] = __ldg(wp + j);

    if (base8 + (U - 1) * THREADS < n8) {
        float v[U][8];
#pragma unroll
        for (int k = 0; k < U; k++)
            ld_v8_cs(x + (size_t)(base8 + k * THREADS) * 8, v[k]);

#pragma unroll
        for (int k = 0; k < U; k++) {
            float r[8];
#pragma unroll
            for (int j = 0; j < 8; j++)
                r[j] = __cosf(v[k][j] + W[j]);
            st_v8_cs(out + (size_t)(base8 + k * THREADS) * 8, r);
        }
    } else {
        // Tail: only the last block (n8 % 1152 != 0) takes this path.
#pragma unroll
        for (int k = 0; k < U; k++) {
            int i = base8 + k * THREADS;
            if (i < n8) {
                float v[8], r[8];
                ld_v8_cs(x + (size_t)i * 8, v);
#pragma unroll
                for (int j = 0; j < 8; j++)
                    r[j] = __cosf(v[j] + W[j]);
                st_v8_cs(out + (size_t)i * 8, r);
            }
        }
    }
}

extern "C" void kernel_launch(void* const* d_in, const int* in_sizes, int n_in,
                              void* d_out, int out_size) {
    const float* x = (const float*)d_in[0];
    const float* w = (const float*)d_in[1];
    float* out = (float*)d_out;

    int n  = in_sizes[0];   // 100663296
    int n8 = n >> 3;        // 12582912 v8s

    int per_block = THREADS * U;     // 1152
    int blocks = (n8 + per_block - 1) / per_block;   // 10923
    qfl_cos_kernel<<<blocks, THREADS>>>(x, w, out, n8);
}

// round 12
// speedup vs baseline: 1.1336x; 1.0134x over previous
#include <cuda_runtime.h>

// out[b, q] = cos(x[b, q] + w[q]),  x: [4194304, 24] f32, w: [24] f32.
// v8 (256-bit) accesses; v8 index i uses weight octet (i % 3). THREADS=192
// divisible by 3 and per-block offset (576*bid) divisible by 3 => octet
// index is the loop-invariant (tid % 3). U=3 front-batched LDG.256 =
// 96B in flight/thread; natural regs ~40 fit under the lb(192,7) cap of
// 48 (cap ABOVE natural — tight caps broke scheduling in R9/R10), giving
// 42 warps/SM: same SM-level in-flight bytes as the U=4/36-warp config
// but with more warps covering issue latency.

#define THREADS 192
#define U 3

__device__ __forceinline__ void ld_v8_cs(const float* p, float* v) {
    asm volatile("ld.global.cs.v8.f32 {%0,%1,%2,%3,%4,%5,%6,%7}, [%8];"
                 : "=f"(v[0]), "=f"(v[1]), "=f"(v[2]), "=f"(v[3]),
                   "=f"(v[4]), "=f"(v[5]), "=f"(v[6]), "=f"(v[7])
                 : "l"(p));
}

__device__ __forceinline__ void st_v8_cs(float* p, const float* v) {
    asm volatile("st.global.cs.v8.f32 [%0], {%1,%2,%3,%4,%5,%6,%7,%8};"
                 :: "l"(p),
                    "f"(v[0]), "f"(v[1]), "f"(v[2]), "f"(v[3]),
                    "f"(v[4]), "f"(v[5]), "f"(v[6]), "f"(v[7])
                 : "memory");
}

__global__ __launch_bounds__(THREADS, 7)
void qfl_cos_kernel(const float* __restrict__ x,
                    const float* __restrict__ w,
                    float* __restrict__ out,
                    int n8) {
    int tid   = threadIdx.x;
    int base8 = blockIdx.x * (THREADS * U) + tid;

    // Loop-invariant weight octet: w[(tid%3)*8 .. +8)
    const float* wp = w + (tid % 3) * 8;
    float W[8];
#pragma unroll
    for (int j = 0; j < 8; j++) W[j] = __ldg(wp + j);

    if (base8 + (U - 1) * THREADS < n8) {
        float v[U][8];
#pragma unroll
        for (int k = 0; k < U; k++)
            ld_v8_cs(x + (size_t)(base8 + k * THREADS) * 8, v[k]);

#pragma unroll
        for (int k = 0; k < U; k++) {
            float r[8];
#pragma unroll
            for (int j = 0; j < 8; j++)
                r[j] = __cosf(v[k][j] + W[j]);
            st_v8_cs(out + (size_t)(base8 + k * THREADS) * 8, r);
        }
    } else {
        // Tail (unused: n8 = 12582912 divisible by THREADS*U = 576)
#pragma unroll
        for (int k = 0; k < U; k++) {
            int i = base8 + k * THREADS;
            if (i < n8) {
                float v[8], r[8];
                ld_v8_cs(x + (size_t)i * 8, v);
#pragma unroll
                for (int j = 0; j < 8; j++)
                    r[j] = __cosf(v[j] + W[j]);
                st_v8_cs(out + (size_t)i * 8, r);
            }
        }
    }
}

extern "C" void kernel_launch(void* const* d_in, const int* in_sizes, int n_in,
                              void* d_out, int out_size) {
    const float* x = (const float*)d_in[0];
    const float* w = (const float*)d_in[1];
    float* out = (float*)d_out;

    int n  = in_sizes[0];   // 100663296
    int n8 = n >> 3;        // 12582912 = 21845.33... -> 576 * 21845 + 192? no:
                            // 12582912 / 576 = 21845.33 -> grid covers tail path
    int per_block = THREADS * U;     // 576
    int blocks = (n8 + per_block - 1) / per_block;   // 21846
    qfl_cos_kernel<<<blocks, THREADS>>>(x, w, out, n8);
}

// round 13
// speedup vs baseline: 1.1339x; 1.0003x over previous
#include <cuda_runtime.h>

// out[b, q] = cos(x[b, q] + w[q]),  x: [4194304, 24] f32, w: [24] f32.
// Converged memory schedule: U=3 front-batched LDG.256 (96B in flight per
// thread, natural 40 regs). v8 index i uses weight octet (i % 3);
// THREADS=384 divisible by 3 and per-block offset (1152*bid) divisible by
// 3 => octet index is loop-invariant (tid % 3). lb(384,4) = 42-reg cap,
// ABOVE the 40-reg natural allocation (tight caps broke the batched
// schedule in R9/R10), giving 48 warps/SM theoretical with fewer, larger
// CTAs than the 192-thread variant.

#define THREADS 384
#define U 3

__device__ __forceinline__ void ld_v8_cs(const float* p, float* v) {
    asm volatile("ld.global.cs.v8.f32 {%0,%1,%2,%3,%4,%5,%6,%7}, [%8];"
                 : "=f"(v[0]), "=f"(v[1]), "=f"(v[2]), "=f"(v[3]),
                   "=f"(v[4]), "=f"(v[5]), "=f"(v[6]), "=f"(v[7])
                 : "l"(p));
}

__device__ __forceinline__ void st_v8_cs(float* p, const float* v) {
    asm volatile("st.global.cs.v8.f32 [%0], {%1,%2,%3,%4,%5,%6,%7,%8};"
                 :: "l"(p),
                    "f"(v[0]), "f"(v[1]), "f"(v[2]), "f"(v[3]),
                    "f"(v[4]), "f"(v[5]), "f"(v[6]), "f"(v[7])
                 : "memory");
}

__global__ __launch_bounds__(THREADS, 4)
void qfl_cos_kernel(const float* __restrict__ x,
                    const float* __restrict__ w,
                    float* __restrict__ out,
                    int n8) {
    int tid   = threadIdx.x;
    int base8 = blockIdx.x * (THREADS * U) + tid;

    // Loop-invariant weight octet: w[(tid%3)*8 .. +8)
    const float* wp = w + (tid % 3) * 8;
    float W[8];
#pragma unroll
    for (int j = 0; j < 8; j++) W[j] = __ldg(wp + j);

    if (base8 + (U - 1) * THREADS < n8) {
        float v[U][8];
#pragma unroll
        for (int k = 0; k < U; k++)
            ld_v8_cs(x + (size_t)(base8 + k * THREADS) * 8, v[k]);

#pragma unroll
        for (int k = 0; k < U; k++) {
            float r[8];
#pragma unroll
            for (int j = 0; j < 8; j++)
                r[j] = __cosf(v[k][j] + W[j]);
            st_v8_cs(out + (size_t)(base8 + k * THREADS) * 8, r);
        }
    } else {
        // Tail: last block only (12582912 % 1152 != 0).
#pragma unroll
        for (int k = 0; k < U; k++) {
            int i = base8 + k * THREADS;
            if (i < n8) {
                float v[8], r[8];
                ld_v8_cs(x + (size_t)i * 8, v);
#pragma unroll
                for (int j = 0; j < 8; j++)
                    r[j] = __cosf(v[j] + W[j]);
                st_v8_cs(out + (size_t)i * 8, r);
            }
        }
    }
}

extern "C" void kernel_launch(void* const* d_in, const int* in_sizes, int n_in,
                              void* d_out, int out_size) {
    const float* x = (const float*)d_in[0];
    const float* w = (const float*)d_in[1];
    float* out = (float*)d_out;

    int n  = in_sizes[0];   // 100663296
    int n8 = n >> 3;        // 12582912 v8s

    int per_block = THREADS * U;     // 1152
    int blocks = (n8 + per_block - 1) / per_block;   // 10923
    qfl_cos_kernel<<<blocks, THREADS>>>(x, w, out, n8);
}